// round 9
// baseline (speedup 1.0000x reference)
#include <cuda_runtime.h>
#include <cuda_bf16.h>
#include <math.h>
#include <stdint.h>

#define NQ   2048
#define NKV  2048
#define AD   1024
#define NH   16
#define KE   3072   // expanded K for bf16 hi/lo split (3 x 1024)

// gate (fp32) + attention operands (bf16 hi/lo)
__device__ float g_gate[NQ * AD];
__device__ __nv_bfloat16 g_qh [NQ  * AD];   // [row][h*64+c]
__device__ __nv_bfloat16 g_ql [NQ  * AD];
__device__ __nv_bfloat16 g_kh [NKV * AD];
__device__ __nv_bfloat16 g_kl [NKV * AD];
__device__ __nv_bfloat16 g_vhT[AD * NKV];   // [h*64+vd][key]  (transposed)
__device__ __nv_bfloat16 g_vlT[AD * NKV];

// bf16 split operands for the projection GEMMs
__device__ __nv_bfloat16 g_aq[NQ  * KE];   // [m][kk]  kk: [hi | hi | lo]
__device__ __nv_bfloat16 g_am[NKV * KE];
__device__ __nv_bfloat16 g_wq[AD * KE];    // [n][kk]  kk: [hi | lo | hi]
__device__ __nv_bfloat16 g_wk[AD * KE];
__device__ __nv_bfloat16 g_wv[AD * KE];
__device__ __nv_bfloat16 g_wg[AD * KE];

__device__ __forceinline__ uint32_t pack_split(float x, float y, uint32_t& lo) {
    __nv_bfloat16 hx = __float2bfloat16(x);
    __nv_bfloat16 hy = __float2bfloat16(y);
    __nv_bfloat16 lx = __float2bfloat16(x - __bfloat162float(hx));
    __nv_bfloat16 ly = __float2bfloat16(y - __bfloat162float(hy));
    lo = ((uint32_t)__bfloat16_as_ushort(ly) << 16) | __bfloat16_as_ushort(lx);
    return ((uint32_t)__bfloat16_as_ushort(hy) << 16) | __bfloat16_as_ushort(hx);
}

__device__ __forceinline__ void cp16(uint32_t dst, const void* src) {
    asm volatile("cp.async.cg.shared.global [%0], [%1], 16;\n" :: "r"(dst), "l"(src));
}
#define CP_COMMIT() asm volatile("cp.async.commit_group;\n" ::: "memory")
#define CP_WAIT1()  asm volatile("cp.async.wait_group 1;\n" ::: "memory")
#define CP_WAIT0()  asm volatile("cp.async.wait_group 0;\n" ::: "memory")

__device__ __forceinline__ void mma16816(
    float c[4], uint32_t a0, uint32_t a1, uint32_t a2, uint32_t a3,
    uint32_t b0, uint32_t b1)
{
    asm volatile(
        "mma.sync.aligned.m16n8k16.row.col.f32.bf16.bf16.f32 "
        "{%0,%1,%2,%3}, {%4,%5,%6,%7}, {%8,%9}, {%0,%1,%2,%3};"
        : "+f"(c[0]), "+f"(c[1]), "+f"(c[2]), "+f"(c[3])
        : "r"(a0), "r"(a1), "r"(a2), "r"(a3), "r"(b0), "r"(b1));
}

__device__ __forceinline__ void ldsm4(
    uint32_t& r0, uint32_t& r1, uint32_t& r2, uint32_t& r3, uint32_t addr)
{
    asm volatile("ldmatrix.sync.aligned.m8n8.x4.shared.b16 {%0,%1,%2,%3}, [%4];"
                 : "=r"(r0), "=r"(r1), "=r"(r2), "=r"(r3) : "r"(addr));
}

// ---------------------------------------------------------------------------
// Convert activations: x -> hi=bf16(x), lo=bf16(x-hi); A'=[hi|hi|lo] along K.
// ---------------------------------------------------------------------------
__global__ __launch_bounds__(256) void conv_a_kernel(
    const float* __restrict__ src0, const float* __restrict__ src1)
{
    const float* src = blockIdx.y ? src1 : src0;
    __nv_bfloat16* dst = blockIdx.y ? g_am : g_aq;
    const int idx = blockIdx.x * 256 + threadIdx.x;
    const int r = idx >> 8;
    const int c = (idx & 255) << 2;
    float4 x = *(const float4*)(src + (size_t)r * 1024 + c);
    float xs[4] = {x.x, x.y, x.z, x.w};
    uint16_t hs[4], ls[4];
    #pragma unroll
    for (int j = 0; j < 4; j++) {
        __nv_bfloat16 h = __float2bfloat16(xs[j]);
        __nv_bfloat16 l = __float2bfloat16(xs[j] - __bfloat162float(h));
        hs[j] = __bfloat16_as_ushort(h);
        ls[j] = __bfloat16_as_ushort(l);
    }
    uint2 hv, lv;
    hv.x = (uint32_t)hs[0] | ((uint32_t)hs[1] << 16);
    hv.y = (uint32_t)hs[2] | ((uint32_t)hs[3] << 16);
    lv.x = (uint32_t)ls[0] | ((uint32_t)ls[1] << 16);
    lv.y = (uint32_t)ls[2] | ((uint32_t)ls[3] << 16);
    __nv_bfloat16* base = dst + (size_t)r * KE + c;
    *(uint2*)(base)        = hv;
    *(uint2*)(base + 1024) = hv;
    *(uint2*)(base + 2048) = lv;
}

// ---------------------------------------------------------------------------
// Convert + transpose weights: W[k][n] -> Wt[n][ [hi(k) | lo(k) | hi(k)] ].
// ---------------------------------------------------------------------------
__global__ void conv_w_kernel(const float* __restrict__ w0, const float* __restrict__ w1,
                              const float* __restrict__ w2, const float* __restrict__ w3)
{
    __shared__ float sm[32][33];
    const float* W; __nv_bfloat16* Wt;
    switch (blockIdx.z) {
        case 0:  W = w0; Wt = g_wq; break;
        case 1:  W = w1; Wt = g_wk; break;
        case 2:  W = w2; Wt = g_wv; break;
        default: W = w3; Wt = g_wg; break;
    }
    const int n0 = blockIdx.x * 32;
    const int k0 = blockIdx.y * 32;
    const int tx = threadIdx.x, ty = threadIdx.y;
    sm[ty][tx] = W[(size_t)(k0 + ty) * 1024 + n0 + tx];
    __syncthreads();
    const float x = sm[tx][ty];
    __nv_bfloat16 h = __float2bfloat16(x);
    __nv_bfloat16 l = __float2bfloat16(x - __bfloat162float(h));
    __nv_bfloat16* p = Wt + (size_t)(n0 + ty) * KE + k0 + tx;
    p[0]    = h;
    p[1024] = l;
    p[2048] = h;
}

// ---------------------------------------------------------------------------
// HMMA projection GEMM, cp.async 3-stage, K-tile=64, double-buffered
// ldmatrix fragment pipeline (load kk+1 while computing kk).
// Stage: sA [128][72], sB [128][72] = 18432 el.
// ---------------------------------------------------------------------------
#define STAGE_EL 18432
#define PIPE_SMEM_BYTES (3 * STAGE_EL * 2)   // 110,592 B

__global__ __launch_bounds__(256, 2) void proj_mma_kernel(const float* __restrict__ qb)
{
    extern __shared__ __nv_bfloat16 ps[];
    const uint32_t sbase = (uint32_t)__cvta_generic_to_shared(ps);

    const int tid  = threadIdx.x;
    const int lane = tid & 31;
    const int wid  = tid >> 5;
    const int wm0  = (wid >> 2) * 64;
    const int wn0  = (wid & 3)  * 32;
    const int z    = blockIdx.z;
    const int n0   = blockIdx.x * 128;
    const int m0   = blockIdx.y * 128;

    const __nv_bfloat16 *Ag, *Bg;
    switch (z) {
        case 0:  Ag = g_aq; Bg = g_wq; break;
        case 1:  Ag = g_am; Bg = g_wk; break;
        case 2:  Ag = g_am; Bg = g_wv; break;
        default: Ag = g_aq; Bg = g_wg; break;
    }
    const __nv_bfloat16* Ab = Ag + (size_t)m0 * KE;
    const __nv_bfloat16* Bb = Bg + (size_t)n0 * KE;

    const int krow = tid >> 2;          // 0..63
    const int seg  = (tid & 3) * 16;    // 0,16,32,48
    const int qr   = lane >> 2;
    const int qc   = (lane & 3) * 2;

    // ldmatrix per-lane byte offsets
    const int g  = lane >> 3;
    const int rr = lane & 7;
    const uint32_t aofs = (uint32_t)((((g & 1) * 8 + rr) * 72 + (g >> 1) * 8) * 2);
    const uint32_t bofs = (uint32_t)(((((g & 2) ? 8 : 0) + rr) * 72 + (g & 1) * 8) * 2);

    auto issue = [&](int t, int s) {
        const int off = t * 64 + seg;
        const __nv_bfloat16* a0 = Ab + (size_t)krow * KE + off;
        const __nv_bfloat16* a1 = Ab + (size_t)(krow + 64) * KE + off;
        const __nv_bfloat16* b0 = Bb + (size_t)krow * KE + off;
        const __nv_bfloat16* b1 = Bb + (size_t)(krow + 64) * KE + off;
        const uint32_t da = sbase + (uint32_t)(s * STAGE_EL + krow * 72 + seg) * 2;
        cp16(da,          a0); cp16(da + 16,          a0 + 8);
        cp16(da + 9216,   a1); cp16(da + 9216 + 16,   a1 + 8);
        cp16(da + 18432,  b0); cp16(da + 18432 + 16,  b0 + 8);
        cp16(da + 27648,  b1); cp16(da + 27648 + 16,  b1 + 8);
        CP_COMMIT();
    };

    issue(0, 0);
    issue(1, 1);

    float acc[4][4][4] = {};
    uint32_t af[2][4][4], bf[2][4][2];

    for (int t = 0; t < 48; t++) {
        const int s = t % 3;
        if (t < 47) CP_WAIT1(); else CP_WAIT0();
        __syncthreads();
        if (t + 2 < 48) issue(t + 2, (t + 2) % 3);

        const uint32_t stA = sbase + (uint32_t)(s * STAGE_EL) * 2;
        const uint32_t stB = stA + 18432;

        auto ldfrags = [&](int buf, int kk) {
            const uint32_t kb = (uint32_t)(kk * 32);
            #pragma unroll
            for (int mt = 0; mt < 4; mt++) {
                const uint32_t a = stA + aofs + (uint32_t)((wm0 + mt * 16) * 144) + kb;
                ldsm4(af[buf][mt][0], af[buf][mt][1], af[buf][mt][2], af[buf][mt][3], a);
            }
            #pragma unroll
            for (int p = 0; p < 2; p++) {
                const uint32_t a = stB + bofs + (uint32_t)((wn0 + p * 16) * 144) + kb;
                ldsm4(bf[buf][2*p][0], bf[buf][2*p][1],
                      bf[buf][2*p+1][0], bf[buf][2*p+1][1], a);
            }
        };

        ldfrags(0, 0);
        #pragma unroll
        for (int kk = 0; kk < 4; kk++) {
            const int b = kk & 1;
            if (kk < 3) ldfrags(b ^ 1, kk + 1);
            #pragma unroll
            for (int mt = 0; mt < 4; mt++)
                #pragma unroll
                for (int nt = 0; nt < 4; nt++)
                    mma16816(acc[mt][nt],
                             af[b][mt][0], af[b][mt][1], af[b][mt][2], af[b][mt][3],
                             bf[b][nt][0], bf[b][nt][1]);
        }
    }

    #pragma unroll
    for (int mt = 0; mt < 4; mt++) {
        #pragma unroll
        for (int nt = 0; nt < 4; nt++) {
            const int rg0 = m0 + wm0 + mt * 16 + qr;
            const int cg  = n0 + wn0 + nt * 8 + qc;
            float v[4] = {acc[mt][nt][0], acc[mt][nt][1],
                          acc[mt][nt][2], acc[mt][nt][3]};
            if (z == 0) {
                const float b0 = qb[cg], b1 = qb[cg + 1];
                v[0] = (v[0] + b0) * 0.125f; v[1] = (v[1] + b1) * 0.125f;
                v[2] = (v[2] + b0) * 0.125f; v[3] = (v[3] + b1) * 0.125f;
            }
            if (z == 0 || z == 1) {
                __nv_bfloat16* H = (z == 0) ? g_qh : g_kh;
                __nv_bfloat16* L = (z == 0) ? g_ql : g_kl;
                uint32_t lo0, lo1;
                uint32_t hi0 = pack_split(v[0], v[1], lo0);
                uint32_t hi1 = pack_split(v[2], v[3], lo1);
                *(uint32_t*)&H[(size_t)rg0 * 1024 + cg]       = hi0;
                *(uint32_t*)&L[(size_t)rg0 * 1024 + cg]       = lo0;
                *(uint32_t*)&H[(size_t)(rg0 + 8) * 1024 + cg] = hi1;
                *(uint32_t*)&L[(size_t)(rg0 + 8) * 1024 + cg] = lo1;
            } else if (z == 2) {
                #pragma unroll
                for (int j = 0; j < 4; j++) {
                    const int col = cg + (j & 1);
                    const int row = rg0 + (j >> 1) * 8;
                    __nv_bfloat16 h = __float2bfloat16(v[j]);
                    __nv_bfloat16 l = __float2bfloat16(v[j] - __bfloat162float(h));
                    g_vhT[(size_t)col * NKV + row] = h;
                    g_vlT[(size_t)col * NKV + row] = l;
                }
            } else {
                #pragma unroll
                for (int j = 0; j < 4; j++)
                    v[j] = 1.0f / (1.0f + __expf(-v[j]));
                *(float2*)(g_gate + (size_t)rg0 * 1024 + cg)       = make_float2(v[0], v[1]);
                *(float2*)(g_gate + (size_t)(rg0 + 8) * 1024 + cg) = make_float2(v[2], v[3]);
            }
        }
    }
}

// ---------------------------------------------------------------------------
// HMMA flash attention, fixed-shift softmax, bias hidden behind QK MMAs,
// software-pipelined ldmatrix fragment loads + interleaved accumulators.
// ---------------------------------------------------------------------------
__global__ __launch_bounds__(256, 2) void attn_kernel(
    const float* __restrict__ bias,
    const float* __restrict__ gate, float* __restrict__ out)
{
    extern __shared__ __nv_bfloat16 sb[];
    const uint32_t sbase = (uint32_t)__cvta_generic_to_shared(sb);

    const int tid  = threadIdx.x;
    const int lane = tid & 31;
    const int wid  = tid >> 5;
    const int qr   = lane >> 2;
    const int qc   = (lane & 3) * 2;
    const int h    = blockIdx.y;
    const int q0   = blockIdx.x * 128;
    const int w16  = wid * 16;

    const int g  = lane >> 3;
    const int rr = lane & 7;
    const uint32_t bofs = (uint32_t)(((((g & 2) ? 8 : 0) + rr) * 72 + (g & 1) * 8) * 2);

    // q fragments, register-resident for all 32 key tiles
    uint32_t qah[16], qal[16];
    {
        const size_t r0 = (size_t)(q0 + w16 + qr) * 1024 + h * 64;
        const size_t r1 = r0 + 8 * 1024;
        #pragma unroll
        for (int ks = 0; ks < 4; ks++) {
            const int c = ks * 16 + qc;
            qah[ks * 4 + 0] = *(const uint32_t*)&g_qh[r0 + c];
            qah[ks * 4 + 1] = *(const uint32_t*)&g_qh[r1 + c];
            qah[ks * 4 + 2] = *(const uint32_t*)&g_qh[r0 + c + 8];
            qah[ks * 4 + 3] = *(const uint32_t*)&g_qh[r1 + c + 8];
            qal[ks * 4 + 0] = *(const uint32_t*)&g_ql[r0 + c];
            qal[ks * 4 + 1] = *(const uint32_t*)&g_ql[r1 + c];
            qal[ks * 4 + 2] = *(const uint32_t*)&g_ql[r0 + c + 8];
            qal[ks * 4 + 3] = *(const uint32_t*)&g_ql[r1 + c + 8];
        }
    }

    const int krow = tid >> 2;          // 0..63
    const int seg  = (tid & 3) * 16;    // 0,16,32,48

    auto issue = [&](int t, int s) {
        const int kt = t * 64;
        const __nv_bfloat16* kh = g_kh + (size_t)(kt + krow) * 1024 + h * 64 + seg;
        const __nv_bfloat16* kl = g_kl + (size_t)(kt + krow) * 1024 + h * 64 + seg;
        const __nv_bfloat16* vh = g_vhT + (size_t)(h * 64 + krow) * NKV + kt + seg;
        const __nv_bfloat16* vl = g_vlT + (size_t)(h * 64 + krow) * NKV + kt + seg;
        const uint32_t db = sbase + (uint32_t)(s * STAGE_EL + krow * 72 + seg) * 2;
        cp16(db,          kh); cp16(db + 16,          kh + 8);
        cp16(db + 9216,   kl); cp16(db + 9216 + 16,   kl + 8);
        cp16(db + 18432,  vh); cp16(db + 18432 + 16,  vh + 8);
        cp16(db + 27648,  vl); cp16(db + 27648 + 16,  vl + 8);
        CP_COMMIT();
    };

    issue(0, 0);
    issue(1, 1);

    float l0 = 0.0f, l1 = 0.0f;
    float oacc[8][4] = {};

    for (int t = 0; t < 32; t++) {
        const int s = t % 3;
        const int kt = t * 64;
        if (t < 31) CP_WAIT1(); else CP_WAIT0();
        __syncthreads();
        if (t + 2 < 32) issue(t + 2, (t + 2) % 3);

        const uint32_t st   = sbase + (uint32_t)(s * STAGE_EL) * 2;
        const uint32_t kh_b = st + bofs;
        const uint32_t kl_b = kh_b + 9216;
        const uint32_t vh_b = kh_b + 18432;
        const uint32_t vl_b = kh_b + 27648;

        const size_t bbase = ((size_t)h * NQ + q0 + w16 + qr) * NKV + kt + qc;

        float sacc[8][4];
        #pragma unroll
        for (int i = 0; i < 8; i++)
            #pragma unroll
            for (int j = 0; j < 4; j++) sacc[i][j] = 0.0f;

        // QK phase: flat 8 steps (p0 + idx>>2, ks = idx&3), pipelined frags,
        // interleaved accumulators.
        auto qk_phase = [&](int p0, float sacc_[8][4]) {
            uint32_t fh[2][4], fe[2][4];
            {
                const uint32_t o = (uint32_t)(p0 * 2304);
                ldsm4(fh[0][0], fh[0][1], fh[0][2], fh[0][3], kh_b + o);
                ldsm4(fe[0][0], fe[0][1], fe[0][2], fe[0][3], kl_b + o);
            }
            #pragma unroll
            for (int idx = 0; idx < 8; idx++) {
                const int b = idx & 1;
                if (idx < 7) {
                    const int ni = idx + 1;
                    const uint32_t o = (uint32_t)((p0 + (ni >> 2)) * 2304 + (ni & 3) * 32);
                    ldsm4(fh[b^1][0], fh[b^1][1], fh[b^1][2], fh[b^1][3], kh_b + o);
                    ldsm4(fe[b^1][0], fe[b^1][1], fe[b^1][2], fe[b^1][3], kl_b + o);
                }
                const int p  = p0 + (idx >> 2);
                const int ks = idx & 3;
                const uint32_t a0 = qah[ks*4+0], a1 = qah[ks*4+1],
                               a2 = qah[ks*4+2], a3 = qah[ks*4+3];
                const uint32_t c0 = qal[ks*4+0], c1 = qal[ks*4+1],
                               c2 = qal[ks*4+2], c3 = qal[ks*4+3];
                mma16816(sacc_[2*p],   a0, a1, a2, a3, fh[b][0], fh[b][1]);
                mma16816(sacc_[2*p+1], a0, a1, a2, a3, fh[b][2], fh[b][3]);
                mma16816(sacc_[2*p],   a0, a1, a2, a3, fe[b][0], fe[b][1]);
                mma16816(sacc_[2*p+1], a0, a1, a2, a3, fe[b][2], fe[b][3]);
                mma16816(sacc_[2*p],   c0, c1, c2, c3, fh[b][0], fh[b][1]);
                mma16816(sacc_[2*p+1], c0, c1, c2, c3, fh[b][2], fh[b][3]);
            }
        };

        // PV phase: flat 8 steps (kv = kv0 + idx>>2, p = idx&3)
        auto pv_phase = [&](int kv0, uint32_t pah[2][4], uint32_t pal[2][4]) {
            uint32_t fh[2][4], fe[2][4];
            {
                const uint32_t o = (uint32_t)(kv0 * 32);
                ldsm4(fh[0][0], fh[0][1], fh[0][2], fh[0][3], vh_b + o);
                ldsm4(fe[0][0], fe[0][1], fe[0][2], fe[0][3], vl_b + o);
            }
            #pragma unroll
            for (int idx = 0; idx < 8; idx++) {
                const int b = idx & 1;
                if (idx < 7) {
                    const int ni = idx + 1;
                    const uint32_t o = (uint32_t)((ni & 3) * 2304 + (kv0 + (ni >> 2)) * 32);
                    ldsm4(fh[b^1][0], fh[b^1][1], fh[b^1][2], fh[b^1][3], vh_b + o);
                    ldsm4(fe[b^1][0], fe[b^1][1], fe[b^1][2], fe[b^1][3], vl_b + o);
                }
                const int kv = idx >> 2;
                const int p  = idx & 3;
                mma16816(oacc[2*p],   pah[kv][0], pah[kv][1], pah[kv][2], pah[kv][3], fh[b][0], fh[b][1]);
                mma16816(oacc[2*p+1], pah[kv][0], pah[kv][1], pah[kv][2], pah[kv][3], fh[b][2], fh[b][3]);
                mma16816(oacc[2*p],   pah[kv][0], pah[kv][1], pah[kv][2], pah[kv][3], fe[b][0], fe[b][1]);
                mma16816(oacc[2*p+1], pah[kv][0], pah[kv][1], pah[kv][2], pah[kv][3], fe[b][2], fe[b][3]);
                mma16816(oacc[2*p],   pal[kv][0], pal[kv][1], pal[kv][2], pal[kv][3], fh[b][0], fh[b][1]);
                mma16816(oacc[2*p+1], pal[kv][0], pal[kv][1], pal[kv][2], pal[kv][3], fh[b][2], fh[b][3]);
            }
        };

        // ---- bias A (keys 0..31), covered by QK phase A
        float2 ba[4][2];
        #pragma unroll
        for (int nt = 0; nt < 4; nt++) {
            ba[nt][0] = *(const float2*)(bias + bbase + nt * 8);
            ba[nt][1] = *(const float2*)(bias + bbase + 8 * NKV + nt * 8);
        }

        qk_phase(0, sacc);

        // fold bias A
        #pragma unroll
        for (int nt = 0; nt < 4; nt++) {
            sacc[nt][0] += ba[nt][0].x; sacc[nt][1] += ba[nt][0].y;
            sacc[nt][2] += ba[nt][1].x; sacc[nt][3] += ba[nt][1].y;
        }
        // bias B (keys 32..63), covered by QK phase B
        #pragma unroll
        for (int nt = 0; nt < 4; nt++) {
            ba[nt][0] = *(const float2*)(bias + bbase + (4 + nt) * 8);
            ba[nt][1] = *(const float2*)(bias + bbase + 8 * NKV + (4 + nt) * 8);
        }

        qk_phase(2, sacc);

        // exp + pack keys 0..31 (overlaps tensor drain of phase B)
        uint32_t pah[2][4], pal[2][4];
        #pragma unroll
        for (int kv = 0; kv < 2; kv++) {
            float e00 = __expf(sacc[2*kv][0]   - 10.0f);
            float e01 = __expf(sacc[2*kv][1]   - 10.0f);
            float e02 = __expf(sacc[2*kv][2]   - 10.0f);
            float e03 = __expf(sacc[2*kv][3]   - 10.0f);
            float e10 = __expf(sacc[2*kv+1][0] - 10.0f);
            float e11 = __expf(sacc[2*kv+1][1] - 10.0f);
            float e12 = __expf(sacc[2*kv+1][2] - 10.0f);
            float e13 = __expf(sacc[2*kv+1][3] - 10.0f);
            l0 += e00 + e01 + e10 + e11;
            l1 += e02 + e03 + e12 + e13;
            pah[kv][0] = pack_split(e00, e01, pal[kv][0]);
            pah[kv][1] = pack_split(e02, e03, pal[kv][1]);
            pah[kv][2] = pack_split(e10, e11, pal[kv][2]);
            pah[kv][3] = pack_split(e12, e13, pal[kv][3]);
        }

        pv_phase(0, pah, pal);

        // fold bias B, exp + pack keys 32..63 (overlaps PV tensor drain)
        #pragma unroll
        for (int nt = 0; nt < 4; nt++) {
            sacc[4+nt][0] += ba[nt][0].x; sacc[4+nt][1] += ba[nt][0].y;
            sacc[4+nt][2] += ba[nt][1].x; sacc[4+nt][3] += ba[nt][1].y;
        }
        #pragma unroll
        for (int kv = 0; kv < 2; kv++) {
            float e00 = __expf(sacc[4+2*kv][0]   - 10.0f);
            float e01 = __expf(sacc[4+2*kv][1]   - 10.0f);
            float e02 = __expf(sacc[4+2*kv][2]   - 10.0f);
            float e03 = __expf(sacc[4+2*kv][3]   - 10.0f);
            float e10 = __expf(sacc[4+2*kv+1][0] - 10.0f);
            float e11 = __expf(sacc[4+2*kv+1][1] - 10.0f);
            float e12 = __expf(sacc[4+2*kv+1][2] - 10.0f);
            float e13 = __expf(sacc[4+2*kv+1][3] - 10.0f);
            l0 += e00 + e01 + e10 + e11;
            l1 += e02 + e03 + e12 + e13;
            pah[kv][0] = pack_split(e00, e01, pal[kv][0]);
            pah[kv][1] = pack_split(e02, e03, pal[kv][1]);
            pah[kv][2] = pack_split(e10, e11, pal[kv][2]);
            pah[kv][3] = pack_split(e12, e13, pal[kv][3]);
        }

        pv_phase(2, pah, pal);
    }

    // final row-sum reduction across the 4 lanes sharing each row
    l0 += __shfl_xor_sync(0xffffffffu, l0, 1);
    l0 += __shfl_xor_sync(0xffffffffu, l0, 2);
    l1 += __shfl_xor_sync(0xffffffffu, l1, 1);
    l1 += __shfl_xor_sync(0xffffffffu, l1, 2);

    // epilogue: normalize + gate; out layout [NQ][H][64]
    const float inv0 = 1.0f / l0;
    const float inv1 = 1.0f / l1;
    const int r0 = q0 + w16 + qr;
    const int r1 = r0 + 8;
    #pragma unroll
    for (int nv = 0; nv < 8; nv++) {
        const int c = nv * 8 + qc;
        float2 gv0 = *(const float2*)(gate + (size_t)r0 * 1024 + h * 64 + c);
        float2 gv1 = *(const float2*)(gate + (size_t)r1 * 1024 + h * 64 + c);
        float2 o0 = make_float2(oacc[nv][0] * inv0 * gv0.x,
                                oacc[nv][1] * inv0 * gv0.y);
        float2 o1 = make_float2(oacc[nv][2] * inv1 * gv1.x,
                                oacc[nv][3] * inv1 * gv1.y);
        *(float2*)(out + ((size_t)r0 * NH + h) * 64 + c) = o0;
        *(float2*)(out + ((size_t)r1 * NH + h) * 64 + c) = o1;
    }
}

// ---------------------------------------------------------------------------
extern "C" void kernel_launch(void* const* d_in, const int* in_sizes, int n_in,
                              void* d_out, int out_size)
{
    const float* q_data   = (const float*)d_in[0];
    const float* m_data   = (const float*)d_in[1];
    const float* bias     = (const float*)d_in[2];
    const float* query_w  = (const float*)d_in[3];
    const float* query_b  = (const float*)d_in[4];
    const float* key_w    = (const float*)d_in[5];
    const float* value_w  = (const float*)d_in[6];
    const float* gating_w = (const float*)d_in[7];
    float* out = (float*)d_out;

    float* dgate;
    cudaGetSymbolAddress((void**)&dgate, g_gate);

    conv_a_kernel<<<dim3(2048, 2), 256>>>(q_data, m_data);
    conv_w_kernel<<<dim3(32, 32, 4), dim3(32, 32)>>>(query_w, key_w, value_w, gating_w);

    cudaFuncSetAttribute(proj_mma_kernel,
                         cudaFuncAttributeMaxDynamicSharedMemorySize,
                         PIPE_SMEM_BYTES);
    proj_mma_kernel<<<dim3(8, 16, 4), 256, PIPE_SMEM_BYTES>>>(query_b);

    cudaFuncSetAttribute(attn_kernel,
                         cudaFuncAttributeMaxDynamicSharedMemorySize,
                         PIPE_SMEM_BYTES);
    attn_kernel<<<dim3(NQ / 128, NH), 256, PIPE_SMEM_BYTES>>>(bias, dgate, out);
}